// round 11
// baseline (speedup 1.0000x reference)
#include <cuda_runtime.h>
#include <cstdint>

// BatchBlur: per-pixel 19x19 blur, reflection pad, weights shared across C=3.
//   input : (2,3,256,256) f32 (361x reuse -> smem patch, float4 xyz=channels)
//   kernel: (2,65536,19,19) f32 (189MB streamed once, gmem->reg via __ldcs)
//   out   : (2,3,256,256) f32 = sum(patch*w)/361
//
// Thread owns 4 adjacent pixels; one input LDS.128 feeds 12 FMAs.
// Warp = 4 groups x 8 subs = 16 pixels of one row. Block = 8 warps = 16x8 tile.
// Weight (ki,kj) of pixel d read at u=kj+d -> unique (s,jj): load-once, coalesced.
// R9: DEPTH-2 pipeline via in-place ping-pong (wA/wB refilled after consumption)
// -> 24 LDGs in flight per warp at the same register budget as depth-1.

#define Hh 256
#define Ww 256
#define HW 65536
#define K2 361
#define TPB 256
#define TILE_W 16
#define TILE_H 8
#define PRR 26            // TILE_H + 18
#define PCC 36            // TILE_W + 18 (+2 pad; max u=21)
#define NP4 (PRR * PCC)   // 936 float4 slots (~15 KB)

__device__ __forceinline__ int reflect_h(int v) {
    return (v < 0) ? -v : ((v >= Hh) ? (2 * Hh - 2 - v) : v);
}

__global__ __launch_bounds__(TPB, 5)
void batchblur_kernel(const float* __restrict__ inp,
                      const float* __restrict__ kw,
                      float* __restrict__ out)
{
    __shared__ float4 s4[NP4];

    const int tid = threadIdx.x;
    const int blk = blockIdx.x;
    const int b   = blk >> 9;             // 512 tiles per batch
    const int t   = blk & 511;
    const int ty0 = (t >> 4) << 3;        // 32 row-tiles of height 8
    const int x0  = (t & 15) << 4;        // 16 col-tiles of width 16

    // ---- stage reflected patch: rows [ty0-9, ty0+16], cols [x0-9, x0+26]
    {
        const float* inb = inp + (size_t)b * (3 * HW);
        for (int i = tid; i < NP4; i += TPB) {
            int r = i / PCC;
            int c = i - r * PCC;
            int y = reflect_h(ty0 + r - 9);
            int x = reflect_h(x0 + c - 9);
            const float* q = inb + y * Ww + x;
            float4 v;
            v.x = __ldg(q);
            v.y = __ldg(q + HW);
            v.z = __ldg(q + 2 * HW);
            v.w = 0.f;
            s4[i] = v;
        }
    }
    __syncthreads();

    // ---- compute
    const int lane = tid & 31;
    const int wr   = tid >> 5;            // warp = tile row 0..7
    const int g    = lane >> 3;           // pixel group 0..3
    const int s    = lane & 7;            // sub-thread 0..7

    const int y  = ty0 + wr;
    const int px = x0 + (g << 2);         // first of 4 pixels
    const size_t p0 = (size_t)b * HW + (size_t)(y * Ww + px);
    const float* wb = kw + p0 * K2 + s;   // + ki*19 + 8*jj + d*360

    const float4* srow = s4 + wr * PCC + (g << 2);

    // Hoisted per-(jj,d) validity (ki-independent)
    bool val[3][4];
    #pragma unroll
    for (int jj = 0; jj < 3; jj++) {
        const int u = s + 8 * jj;
        #pragma unroll
        for (int d = 0; d < 4; d++) {
            const int kj = u - d;
            val[jj][d] = (u <= 21) && (kj >= 0) && (kj <= 18);
        }
    }
    const bool uok1 = (s + 8  <= 21);
    const bool uok2 = (s + 16 <= 21);

    float a00=0,a01=0,a02=0, a10=0,a11=0,a12=0;
    float a20=0,a21=0,a22=0, a30=0,a31=0,a32=0;

    float wA[12], wB[12];

    // prologue: rows 0 and 1 in flight
    #pragma unroll
    for (int jj = 0; jj < 3; jj++)
        #pragma unroll
        for (int d = 0; d < 4; d++) {
            const int o = 8 * jj + d * 360;
            wA[jj * 4 + d] = val[jj][d] ? __ldcs(wb + o)      : 0.f;
            wB[jj * 4 + d] = val[jj][d] ? __ldcs(wb + 19 + o) : 0.f;
        }

#define CONSUME(W, KI)                                                         \
    do {                                                                       \
        const float4* sr = srow + (KI) * PCC;                                  \
        {                                                                      \
            const float4 v = sr[s];                                            \
            a00 += (W)[0]*v.x; a01 += (W)[0]*v.y; a02 += (W)[0]*v.z;           \
            a10 += (W)[1]*v.x; a11 += (W)[1]*v.y; a12 += (W)[1]*v.z;           \
            a20 += (W)[2]*v.x; a21 += (W)[2]*v.y; a22 += (W)[2]*v.z;           \
            a30 += (W)[3]*v.x; a31 += (W)[3]*v.y; a32 += (W)[3]*v.z;           \
        }                                                                      \
        if (uok1) {                                                            \
            const float4 v = sr[s + 8];                                        \
            a00 += (W)[4]*v.x; a01 += (W)[4]*v.y; a02 += (W)[4]*v.z;           \
            a10 += (W)[5]*v.x; a11 += (W)[5]*v.y; a12 += (W)[5]*v.z;           \
            a20 += (W)[6]*v.x; a21 += (W)[6]*v.y; a22 += (W)[6]*v.z;           \
            a30 += (W)[7]*v.x; a31 += (W)[7]*v.y; a32 += (W)[7]*v.z;           \
        }                                                                      \
        if (uok2) {                                                            \
            const float4 v = sr[s + 16];                                       \
            a00 += (W)[8] *v.x; a01 += (W)[8] *v.y; a02 += (W)[8] *v.z;        \
            a10 += (W)[9] *v.x; a11 += (W)[9] *v.y; a12 += (W)[9] *v.z;        \
            a20 += (W)[10]*v.x; a21 += (W)[10]*v.y; a22 += (W)[10]*v.z;        \
            a30 += (W)[11]*v.x; a31 += (W)[11]*v.y; a32 += (W)[11]*v.z;        \
        }                                                                      \
    } while (0)

#define REFILL(W, KI)                                                          \
    do {                                                                       \
        const bool ok = (KI) < 19;                                             \
        const float* wrow = wb + (KI) * 19;                                    \
        _Pragma("unroll")                                                      \
        for (int jj = 0; jj < 3; jj++) {                                       \
            _Pragma("unroll")                                                  \
            for (int d = 0; d < 4; d++)                                        \
                (W)[jj * 4 + d] = (ok && val[jj][d])                           \
                                ? __ldcs(wrow + 8 * jj + d * 360) : 0.f;       \
        }                                                                      \
    } while (0)

    #pragma unroll 1
    for (int ki = 0; ki < 18; ki += 2) {
        CONSUME(wA, ki);
        REFILL(wA, ki + 2);
        CONSUME(wB, ki + 1);
        REFILL(wB, ki + 3);
    }
    CONSUME(wA, 18);                      // ki = 18 (wA holds row 18)

#undef CONSUME
#undef REFILL

    // ---- reduce over the 8 sub-threads (xor 1,2,4 stays inside each group)
    #pragma unroll
    for (int m = 1; m <= 4; m <<= 1) {
        a00 += __shfl_xor_sync(0xffffffffu, a00, m);
        a01 += __shfl_xor_sync(0xffffffffu, a01, m);
        a02 += __shfl_xor_sync(0xffffffffu, a02, m);
        a10 += __shfl_xor_sync(0xffffffffu, a10, m);
        a11 += __shfl_xor_sync(0xffffffffu, a11, m);
        a12 += __shfl_xor_sync(0xffffffffu, a12, m);
        a20 += __shfl_xor_sync(0xffffffffu, a20, m);
        a21 += __shfl_xor_sync(0xffffffffu, a21, m);
        a22 += __shfl_xor_sync(0xffffffffu, a22, m);
        a30 += __shfl_xor_sync(0xffffffffu, a30, m);
        a31 += __shfl_xor_sync(0xffffffffu, a31, m);
        a32 += __shfl_xor_sync(0xffffffffu, a32, m);
    }

    if (s < 4) {                          // lane s writes pixel px+s
        float c0, c1, c2;
        if (s == 0) { c0=a00; c1=a01; c2=a02; }
        if (s == 1) { c0=a10; c1=a11; c2=a12; }
        if (s == 2) { c0=a20; c1=a21; c2=a22; }
        if (s == 3) { c0=a30; c1=a31; c2=a32; }
        const float inv = 1.0f / 361.0f;
        float* ob = out + (size_t)b * (3 * HW) + (y * Ww + px + s);
        ob[0]      = c0 * inv;
        ob[HW]     = c1 * inv;
        ob[2 * HW] = c2 * inv;
    }
}

extern "C" void kernel_launch(void* const* d_in, const int* in_sizes, int n_in,
                              void* d_out, int out_size)
{
    const float* inp = (const float*)d_in[0];
    const float* kw  = (const float*)d_in[1];
    if (n_in >= 2 && in_sizes[0] > in_sizes[1]) {   // big tensor = weights
        inp = (const float*)d_in[1];
        kw  = (const float*)d_in[0];
    }
    const int grid = 2 * (Hh / TILE_H) * (Ww / TILE_W);   // 1024 blocks
    batchblur_kernel<<<grid, TPB>>>(inp, kw, (float*)d_out);
}

// round 13
// speedup vs baseline: 1.0737x; 1.0737x over previous
#include <cuda_runtime.h>
#include <cstdint>

// BatchBlur: per-pixel 19x19 blur, reflection pad, weights shared across C=3.
//   input : (2,3,256,256) f32 (361x reuse -> smem patch, float4 xyz=channels)
//   kernel: (2,65536,19,19) f32 (189MB streamed once, gmem->reg via __ldcs)
//   out   : (2,3,256,256) f32 = sum(patch*w)/361
//
// Thread owns 4 adjacent pixels; one input LDS.128 feeds 12 FMAs.
// Warp = 4 groups x 8 subs = 16 pixels of one row. Block = 8 warps = 16x8 tile.
// Weight (ki,kj) of pixel d read at u=kj+d -> unique (s,jj): load-once, coalesced.
// Depth-2 pipeline via in-place ping-pong (wA/wB refilled after consumption)
// -> 24 LDGs in flight per warp at the depth-1 register budget.
// (Macros replaced by lambdas; semantics identical.)

#define Hh 256
#define Ww 256
#define HW 65536
#define K2 361
#define TPB 256
#define TILE_W 16
#define TILE_H 8
#define PRR 26            // TILE_H + 18
#define PCC 36            // TILE_W + 18 (+2 pad; max u=21)
#define NP4 (PRR * PCC)   // 936 float4 slots (~15 KB)

__device__ __forceinline__ int reflect_h(int v) {
    return (v < 0) ? -v : ((v >= Hh) ? (2 * Hh - 2 - v) : v);
}

__global__ __launch_bounds__(TPB, 5)
void batchblur_kernel(const float* __restrict__ inp,
                      const float* __restrict__ kw,
                      float* __restrict__ out)
{
    __shared__ float4 s4[NP4];

    const int tid = threadIdx.x;
    const int blk = blockIdx.x;
    const int b   = blk >> 9;             // 512 tiles per batch
    const int t   = blk & 511;
    const int ty0 = (t >> 4) << 3;        // 32 row-tiles of height 8
    const int x0  = (t & 15) << 4;        // 16 col-tiles of width 16

    // ---- stage reflected patch: rows [ty0-9, ty0+16], cols [x0-9, x0+26]
    {
        const float* inb = inp + (size_t)b * (3 * HW);
        for (int i = tid; i < NP4; i += TPB) {
            int r = i / PCC;
            int c = i - r * PCC;
            int y = reflect_h(ty0 + r - 9);
            int x = reflect_h(x0 + c - 9);
            const float* q = inb + y * Ww + x;
            float4 v;
            v.x = __ldg(q);
            v.y = __ldg(q + HW);
            v.z = __ldg(q + 2 * HW);
            v.w = 0.f;
            s4[i] = v;
        }
    }
    __syncthreads();

    // ---- compute
    const int lane = tid & 31;
    const int wr   = tid >> 5;            // warp = tile row 0..7
    const int g    = lane >> 3;           // pixel group 0..3
    const int s    = lane & 7;            // sub-thread 0..7

    const int y  = ty0 + wr;
    const int px = x0 + (g << 2);         // first of 4 pixels
    const size_t p0 = (size_t)b * HW + (size_t)(y * Ww + px);
    const float* wb = kw + p0 * K2 + s;   // + ki*19 + 8*jj + d*360

    const float4* srow = s4 + wr * PCC + (g << 2);

    // Hoisted per-(jj,d) validity (ki-independent)
    bool val[3][4];
    #pragma unroll
    for (int jj = 0; jj < 3; jj++) {
        const int u = s + 8 * jj;
        #pragma unroll
        for (int d = 0; d < 4; d++) {
            const int kj = u - d;
            val[jj][d] = (u <= 21) && (kj >= 0) && (kj <= 18);
        }
    }
    const bool uok1 = (s + 8  <= 21);
    const bool uok2 = (s + 16 <= 21);

    float a00=0,a01=0,a02=0, a10=0,a11=0,a12=0;
    float a20=0,a21=0,a22=0, a30=0,a31=0,a32=0;

    float wA[12], wB[12];

    auto refill = [&](float (&W)[12], int KI) {
        const bool ok = KI < 19;
        const float* wrow = wb + KI * 19;
        #pragma unroll
        for (int jj = 0; jj < 3; jj++) {
            #pragma unroll
            for (int d = 0; d < 4; d++)
                W[jj * 4 + d] = (ok && val[jj][d])
                              ? __ldcs(wrow + 8 * jj + d * 360) : 0.f;
        }
    };

    auto consume = [&](const float (&W)[12], int KI) {
        const float4* sr = srow + KI * PCC;
        {
            const float4 v = sr[s];
            a00 += W[0]*v.x; a01 += W[0]*v.y; a02 += W[0]*v.z;
            a10 += W[1]*v.x; a11 += W[1]*v.y; a12 += W[1]*v.z;
            a20 += W[2]*v.x; a21 += W[2]*v.y; a22 += W[2]*v.z;
            a30 += W[3]*v.x; a31 += W[3]*v.y; a32 += W[3]*v.z;
        }
        if (uok1) {
            const float4 v = sr[s + 8];
            a00 += W[4]*v.x; a01 += W[4]*v.y; a02 += W[4]*v.z;
            a10 += W[5]*v.x; a11 += W[5]*v.y; a12 += W[5]*v.z;
            a20 += W[6]*v.x; a21 += W[6]*v.y; a22 += W[6]*v.z;
            a30 += W[7]*v.x; a31 += W[7]*v.y; a32 += W[7]*v.z;
        }
        if (uok2) {
            const float4 v = sr[s + 16];
            a00 += W[8] *v.x; a01 += W[8] *v.y; a02 += W[8] *v.z;
            a10 += W[9] *v.x; a11 += W[9] *v.y; a12 += W[9] *v.z;
            a20 += W[10]*v.x; a21 += W[10]*v.y; a22 += W[10]*v.z;
            a30 += W[11]*v.x; a31 += W[11]*v.y; a32 += W[11]*v.z;
        }
    };

    // prologue: rows 0 and 1 in flight
    refill(wA, 0);
    refill(wB, 1);

    #pragma unroll 1
    for (int ki = 0; ki < 18; ki += 2) {
        consume(wA, ki);
        refill(wA, ki + 2);
        consume(wB, ki + 1);
        refill(wB, ki + 3);
    }
    consume(wA, 18);                      // ki = 18 (wA holds row 18)

    // ---- reduce over the 8 sub-threads (xor 1,2,4 stays inside each group)
    #pragma unroll
    for (int m = 1; m <= 4; m <<= 1) {
        a00 += __shfl_xor_sync(0xffffffffu, a00, m);
        a01 += __shfl_xor_sync(0xffffffffu, a01, m);
        a02 += __shfl_xor_sync(0xffffffffu, a02, m);
        a10 += __shfl_xor_sync(0xffffffffu, a10, m);
        a11 += __shfl_xor_sync(0xffffffffu, a11, m);
        a12 += __shfl_xor_sync(0xffffffffu, a12, m);
        a20 += __shfl_xor_sync(0xffffffffu, a20, m);
        a21 += __shfl_xor_sync(0xffffffffu, a21, m);
        a22 += __shfl_xor_sync(0xffffffffu, a22, m);
        a30 += __shfl_xor_sync(0xffffffffu, a30, m);
        a31 += __shfl_xor_sync(0xffffffffu, a31, m);
        a32 += __shfl_xor_sync(0xffffffffu, a32, m);
    }

    if (s < 4) {                          // lane s writes pixel px+s
        float c0, c1, c2;
        if (s == 0) { c0=a00; c1=a01; c2=a02; }
        if (s == 1) { c0=a10; c1=a11; c2=a12; }
        if (s == 2) { c0=a20; c1=a21; c2=a22; }
        if (s == 3) { c0=a30; c1=a31; c2=a32; }
        const float inv = 1.0f / 361.0f;
        float* ob = out + (size_t)b * (3 * HW) + (y * Ww + px + s);
        ob[0]      = c0 * inv;
        ob[HW]     = c1 * inv;
        ob[2 * HW] = c2 * inv;
    }
}

extern "C" void kernel_launch(void* const* d_in, const int* in_sizes, int n_in,
                              void* d_out, int out_size)
{
    const float* inp = (const float*)d_in[0];
    const float* kw  = (const float*)d_in[1];
    if (n_in >= 2 && in_sizes[0] > in_sizes[1]) {   // big tensor = weights
        inp = (const float*)d_in[1];
        kw  = (const float*)d_in[0];
    }
    const int grid = 2 * (Hh / TILE_H) * (Ww / TILE_W);   // 1024 blocks
    batchblur_kernel<<<grid, TPB>>>(inp, kw, (float*)d_out);
}

// round 14
// speedup vs baseline: 1.3607x; 1.2673x over previous
#include <cuda_runtime.h>
#include <cstdint>

// BatchBlur: per-pixel 19x19 blur, reflection pad, weights shared across C=3.
//   input : (2,3,256,256) f32 (361x reuse -> smem patch, float4 xyz=channels)
//   kernel: (2,65536,19,19) f32 (189MB streamed once, gmem->reg via __ldcs)
//   out   : (2,3,256,256) f32 = sum(patch*w)/361
//
// Thread owns 4 adjacent pixels; one input LDS.128 feeds 12 FMAs.
// Warp = 4 groups x 8 subs = 16 pixels of one row. Block = 8 warps = 16x8 tile.
// Weight (ki,kj) of pixel d read at u=kj+d -> unique (s,jj): load-once, coalesced.
// R14: 3-buffer rotation, LOADS ISSUED BEFORE THE STALLING FMAs every step
// (fixes R13's in-place ping-pong that put the stall ahead of the loads).
// Steady state: ~24 LDGs in flight per warp, load->use distance = 2 rows.

#define Hh 256
#define Ww 256
#define HW 65536
#define K2 361
#define TPB 256
#define TILE_W 16
#define TILE_H 8
#define PRR 26            // TILE_H + 18
#define PCC 36            // TILE_W + 18 (+2 pad; max u=21)
#define NP4 (PRR * PCC)   // 936 float4 slots (~15 KB)

__device__ __forceinline__ int reflect_h(int v) {
    return (v < 0) ? -v : ((v >= Hh) ? (2 * Hh - 2 - v) : v);
}

__global__ __launch_bounds__(TPB, 4)
void batchblur_kernel(const float* __restrict__ inp,
                      const float* __restrict__ kw,
                      float* __restrict__ out)
{
    __shared__ float4 s4[NP4];

    const int tid = threadIdx.x;
    const int blk = blockIdx.x;
    const int b   = blk >> 9;             // 512 tiles per batch
    const int t   = blk & 511;
    const int ty0 = (t >> 4) << 3;        // 32 row-tiles of height 8
    const int x0  = (t & 15) << 4;        // 16 col-tiles of width 16

    // ---- stage reflected patch: rows [ty0-9, ty0+16], cols [x0-9, x0+26]
    {
        const float* inb = inp + (size_t)b * (3 * HW);
        for (int i = tid; i < NP4; i += TPB) {
            int r = i / PCC;
            int c = i - r * PCC;
            int y = reflect_h(ty0 + r - 9);
            int x = reflect_h(x0 + c - 9);
            const float* q = inb + y * Ww + x;
            float4 v;
            v.x = __ldg(q);
            v.y = __ldg(q + HW);
            v.z = __ldg(q + 2 * HW);
            v.w = 0.f;
            s4[i] = v;
        }
    }
    __syncthreads();

    // ---- compute
    const int lane = tid & 31;
    const int wr   = tid >> 5;            // warp = tile row 0..7
    const int g    = lane >> 3;           // pixel group 0..3
    const int s    = lane & 7;            // sub-thread 0..7

    const int y  = ty0 + wr;
    const int px = x0 + (g << 2);         // first of 4 pixels
    const size_t p0 = (size_t)b * HW + (size_t)(y * Ww + px);
    const float* wb = kw + p0 * K2 + s;   // + ki*19 + 8*jj + d*360

    const float4* srow = s4 + wr * PCC + (g << 2);

    // Hoisted per-(jj,d) validity (ki-independent)
    bool val[3][4];
    #pragma unroll
    for (int jj = 0; jj < 3; jj++) {
        const int u = s + 8 * jj;
        #pragma unroll
        for (int d = 0; d < 4; d++) {
            const int kj = u - d;
            val[jj][d] = (u <= 21) && (kj >= 0) && (kj <= 18);
        }
    }
    const bool uok1 = (s + 8  <= 21);
    const bool uok2 = (s + 16 <= 21);

    float a00=0,a01=0,a02=0, a10=0,a11=0,a12=0;
    float a20=0,a21=0,a22=0, a30=0,a31=0,a32=0;

    float wA[12], wB[12], wC[12];

    auto refill = [&](float (&W)[12], int KI) {
        const bool ok = KI < 19;
        const float* wrow = wb + KI * 19;
        #pragma unroll
        for (int jj = 0; jj < 3; jj++) {
            #pragma unroll
            for (int d = 0; d < 4; d++)
                W[jj * 4 + d] = (ok && val[jj][d])
                              ? __ldcs(wrow + 8 * jj + d * 360) : 0.f;
        }
    };

    auto consume = [&](const float (&W)[12], int KI) {
        const float4* sr = srow + KI * PCC;
        {
            const float4 v = sr[s];
            a00 += W[0]*v.x; a01 += W[0]*v.y; a02 += W[0]*v.z;
            a10 += W[1]*v.x; a11 += W[1]*v.y; a12 += W[1]*v.z;
            a20 += W[2]*v.x; a21 += W[2]*v.y; a22 += W[2]*v.z;
            a30 += W[3]*v.x; a31 += W[3]*v.y; a32 += W[3]*v.z;
        }
        if (uok1) {
            const float4 v = sr[s + 8];
            a00 += W[4]*v.x; a01 += W[4]*v.y; a02 += W[4]*v.z;
            a10 += W[5]*v.x; a11 += W[5]*v.y; a12 += W[5]*v.z;
            a20 += W[6]*v.x; a21 += W[6]*v.y; a22 += W[6]*v.z;
            a30 += W[7]*v.x; a31 += W[7]*v.y; a32 += W[7]*v.z;
        }
        if (uok2) {
            const float4 v = sr[s + 16];
            a00 += W[8] *v.x; a01 += W[8] *v.y; a02 += W[8] *v.z;
            a10 += W[9] *v.x; a11 += W[9] *v.y; a12 += W[9] *v.z;
            a20 += W[10]*v.x; a21 += W[10]*v.y; a22 += W[10]*v.z;
            a30 += W[11]*v.x; a31 += W[11]*v.y; a32 += W[11]*v.z;
        }
    };

    // prologue: rows 0 (A) and 1 (B) in flight
    refill(wA, 0);
    refill(wB, 1);

    // steady state, unrolled by 3 to rotate A,B,C without copies.
    // Invariant at phase start: A=row ki (arrived), B=ki+1 (in flight), C=free.
    // Loads are ALWAYS issued before the consuming (stalling) FMAs.
    #pragma unroll 1
    for (int ki = 0; ki < 18; ki += 3) {
        refill(wC, ki + 2);  consume(wA, ki);
        refill(wA, ki + 3);  consume(wB, ki + 1);
        refill(wB, ki + 4);  consume(wC, ki + 2);
    }
    consume(wA, 18);                      // row 18 (loaded at ki=15 phase 2)

    // ---- reduce over the 8 sub-threads (xor 1,2,4 stays inside each group)
    #pragma unroll
    for (int m = 1; m <= 4; m <<= 1) {
        a00 += __shfl_xor_sync(0xffffffffu, a00, m);
        a01 += __shfl_xor_sync(0xffffffffu, a01, m);
        a02 += __shfl_xor_sync(0xffffffffu, a02, m);
        a10 += __shfl_xor_sync(0xffffffffu, a10, m);
        a11 += __shfl_xor_sync(0xffffffffu, a11, m);
        a12 += __shfl_xor_sync(0xffffffffu, a12, m);
        a20 += __shfl_xor_sync(0xffffffffu, a20, m);
        a21 += __shfl_xor_sync(0xffffffffu, a21, m);
        a22 += __shfl_xor_sync(0xffffffffu, a22, m);
        a30 += __shfl_xor_sync(0xffffffffu, a30, m);
        a31 += __shfl_xor_sync(0xffffffffu, a31, m);
        a32 += __shfl_xor_sync(0xffffffffu, a32, m);
    }

    if (s < 4) {                          // lane s writes pixel px+s
        float c0, c1, c2;
        if (s == 0) { c0=a00; c1=a01; c2=a02; }
        if (s == 1) { c0=a10; c1=a11; c2=a12; }
        if (s == 2) { c0=a20; c1=a21; c2=a22; }
        if (s == 3) { c0=a30; c1=a31; c2=a32; }
        const float inv = 1.0f / 361.0f;
        float* ob = out + (size_t)b * (3 * HW) + (y * Ww + px + s);
        ob[0]      = c0 * inv;
        ob[HW]     = c1 * inv;
        ob[2 * HW] = c2 * inv;
    }
}

extern "C" void kernel_launch(void* const* d_in, const int* in_sizes, int n_in,
                              void* d_out, int out_size)
{
    const float* inp = (const float*)d_in[0];
    const float* kw  = (const float*)d_in[1];
    if (n_in >= 2 && in_sizes[0] > in_sizes[1]) {   // big tensor = weights
        inp = (const float*)d_in[1];
        kw  = (const float*)d_in[0];
    }
    const int grid = 2 * (Hh / TILE_H) * (Ww / TILE_W);   // 1024 blocks
    batchblur_kernel<<<grid, TPB>>>(inp, kw, (float*)d_out);
}